// round 1
// baseline (speedup 1.0000x reference)
#include <cuda_runtime.h>
#include <math.h>

#define NSLOT 9
#define DD    64

// Precomputed per-batch tables (B <= 2 for this problem).
__device__ float g_ck[2][NSLOT][DD];   // SCALE * Wq^T k_j
__device__ float g_c0[2][NSLOT];       // SCALE * Wq_b . k_j
__device__ float g_M [2][NSLOT][DD];   // slots_full[j] @ out_w^T
__device__ float g_sscale;             // exp(density_scale)

__global__ void precompute_kernel(const float* __restrict__ slots,
                                  const float* __restrict__ empty_slot,
                                  const float* __restrict__ Wq_w,
                                  const float* __restrict__ Wq_b,
                                  const float* __restrict__ Wk_w,
                                  const float* __restrict__ Wk_b,
                                  const float* __restrict__ out_w,
                                  const float* __restrict__ density_scale)
{
    const int b = blockIdx.x;
    const int d = threadIdx.x;           // 0..63
    __shared__ float sf[NSLOT][DD];      // slots_full
    __shared__ float kv[NSLOT][DD];      // k vectors

    for (int idx = d; idx < NSLOT * DD; idx += DD) {
        int j = idx >> 6, s = idx & 63;
        sf[j][s] = (j == 0) ? empty_slot[s]
                            : slots[((size_t)b * 8 + (j - 1)) * DD + s];
    }
    __syncthreads();

    // k_j[d] = sum_s sf[j][s] * Wk_w[d][s] + Wk_b[d]
    // M[j][d] = sum_s sf[j][s] * out_w[d][s]
    for (int j = 0; j < NSLOT; ++j) {
        float aK = Wk_b[d], aM = 0.f;
        #pragma unroll 8
        for (int s = 0; s < DD; ++s) {
            float sv = sf[j][s];
            aK = fmaf(sv, Wk_w[d * DD + s], aK);
            aM = fmaf(sv, out_w[d * DD + s], aM);
        }
        kv[j][d] = aK;
        g_M[b][j][d] = aM;
    }
    __syncthreads();

    const float scale = 0.125f;  // 64^-0.5
    // ck[j][e] = SCALE * sum_d Wq_w[d][e] * k_j[d]   (thread index = e)
    for (int j = 0; j < NSLOT; ++j) {
        float a = 0.f;
        #pragma unroll 8
        for (int dd = 0; dd < DD; ++dd)
            a = fmaf(Wq_w[dd * DD + d], kv[j][dd], a);
        g_ck[b][j][d] = a * scale;
    }
    if (d < NSLOT) {
        float a = 0.f;
        for (int dd = 0; dd < DD; ++dd)
            a = fmaf(Wq_b[dd], kv[d][dd], a);
        g_c0[b][d] = a * scale;
    }
    if (b == 0 && d == 0) g_sscale = expf(density_scale[0]);
}

__global__ void __launch_bounds__(256)
points_kernel(const float* __restrict__ x,
              const float* __restrict__ coor,
              float* __restrict__ xo,
              float* __restrict__ wout,
              float* __restrict__ sig,
              const float* __restrict__ out_b,
              int Npts)
{
    __shared__ float4 sCK[NSLOT * 16];
    __shared__ float4 sM [NSLOT * 16];
    __shared__ float4 sOB[16];
    __shared__ float  sC0[NSLOT];
    __shared__ float  sScale;

    const int b = blockIdx.y;
    const int t = threadIdx.x;

    {
        const float4* gck = (const float4*)&g_ck[b][0][0];
        const float4* gm  = (const float4*)&g_M [b][0][0];
        for (int i = t; i < NSLOT * 16; i += blockDim.x) {
            sCK[i] = gck[i];
            sM [i] = gm [i];
        }
        if (t < NSLOT) sC0[t] = g_c0[b][t];
        if (t < 16)    sOB[t] = ((const float4*)out_b)[t];
        if (t == 0)    sScale = g_sscale;
    }
    __syncthreads();

    const int p = blockIdx.x * blockDim.x + t;
    if (p >= Npts) return;
    const size_t base = (size_t)b * Npts + p;

    // -------- logits: acc[j] = c0[j] + x . ck[j] --------
    const float4* xp = (const float4*)(x + base * DD);
    float acc[NSLOT];
    #pragma unroll
    for (int j = 0; j < NSLOT; ++j) acc[j] = sC0[j];

    #pragma unroll
    for (int c = 0; c < 16; ++c) {
        float4 xv = xp[c];
        #pragma unroll
        for (int j = 0; j < NSLOT; ++j) {
            float4 cv = sCK[j * 16 + c];
            acc[j] = fmaf(xv.x, cv.x, acc[j]);
            acc[j] = fmaf(xv.y, cv.y, acc[j]);
            acc[j] = fmaf(xv.z, cv.z, acc[j]);
            acc[j] = fmaf(xv.w, cv.w, acc[j]);
        }
    }

    // -------- oob mask --------
    const float* cp = coor + base * 3;
    bool oob = (fabsf(cp[0]) > 1.0f) || (fabsf(cp[1]) > 1.0f) || (fabsf(cp[2]) > 1.0f);
    const int kmax = oob ? 2 : NSLOT;

    // -------- softmax over active slots --------
    float m = fmaxf(acc[0], acc[1]);
    if (!oob) {
        #pragma unroll
        for (int j = 2; j < NSLOT; ++j) m = fmaxf(m, acc[j]);
    }
    float w[NSLOT];
    float sum = 0.f;
    #pragma unroll
    for (int j = 0; j < NSLOT; ++j) {
        float e = (j < kmax) ? __expf(acc[j] - m) : 0.f;
        w[j] = e;
        sum += e;
    }
    const float inv = __frcp_rn(sum);

    // -------- sigma = sum_{j>=1} relu(logit_j) * w_j * exp(ds) --------
    float sg = 0.f;
    #pragma unroll
    for (int j = 1; j < NSLOT; ++j)
        sg = fmaf(fmaxf(acc[j], 0.f), w[j], sg);
    sg *= inv * sScale;

    #pragma unroll
    for (int j = 0; j < NSLOT; ++j) w[j] *= inv;

    // -------- store w, sigma --------
    float* wp = wout + base * (size_t)NSLOT;
    #pragma unroll
    for (int j = 0; j < NSLOT; ++j) wp[j] = w[j];
    sig[base] = sg;

    // -------- xo[d] = out_b[d] + sum_j w[j] * M[j][d] --------
    float4* op = (float4*)(xo + base * DD);
    #pragma unroll
    for (int c = 0; c < 16; ++c) {
        float4 o = sOB[c];
        #pragma unroll
        for (int j = 0; j < NSLOT; ++j) {
            float4 mv = sM[j * 16 + c];
            o.x = fmaf(w[j], mv.x, o.x);
            o.y = fmaf(w[j], mv.y, o.y);
            o.z = fmaf(w[j], mv.z, o.z);
            o.w = fmaf(w[j], mv.w, o.w);
        }
        op[c] = o;
    }
}

extern "C" void kernel_launch(void* const* d_in, const int* in_sizes, int n_in,
                              void* d_out, int out_size)
{
    const float* point_feats   = (const float*)d_in[0];
    // d_in[1] = points_emb (unused by the scored block)
    const float* slots         = (const float*)d_in[2];
    const float* coor          = (const float*)d_in[3];
    const float* empty_slot    = (const float*)d_in[4];
    const float* Wq_w          = (const float*)d_in[5];
    const float* Wq_b          = (const float*)d_in[6];
    const float* Wk_w          = (const float*)d_in[7];
    const float* Wk_b          = (const float*)d_in[8];
    const float* out_w         = (const float*)d_in[9];
    const float* out_b         = (const float*)d_in[10];
    const float* density_scale = (const float*)d_in[11];

    const int B    = in_sizes[2] / (8 * 64);      // slots: [B, 8, 64]
    const int Npts = in_sizes[0] / (B * 64);      // point_feats: [B, N, 64]

    float* xo   = (float*)d_out;                                  // [B, N, 64]
    float* wout = xo + (size_t)B * Npts * 64;                     // [B, N, 9]
    float* sig  = wout + (size_t)B * Npts * 9;                    // [B, N]

    precompute_kernel<<<B, 64>>>(slots, empty_slot, Wq_w, Wq_b,
                                 Wk_w, Wk_b, out_w, density_scale);

    dim3 grid((Npts + 255) / 256, B);
    points_kernel<<<grid, 256>>>(point_feats, coor, xo, wout, sig, out_b, Npts);
}

// round 2
// speedup vs baseline: 1.6174x; 1.6174x over previous
#include <cuda_runtime.h>
#include <math.h>
#include <stdint.h>

#define NSLOT 9
#define DD    64
#define TILE  128   // points per block
#define BLK   128   // threads per block

typedef unsigned long long u64;

// ---------------- packed f32x2 helpers ----------------
__device__ __forceinline__ u64 ffma2(u64 a, u64 b, u64 c) {
    u64 d;
    asm("fma.rn.f32x2 %0, %1, %2, %3;" : "=l"(d) : "l"(a), "l"(b), "l"(c));
    return d;
}
__device__ __forceinline__ u64 pack2(float x, float y) {
    u64 r; asm("mov.b64 %0, {%1, %2};" : "=l"(r) : "f"(x), "f"(y)); return r;
}
__device__ __forceinline__ u64 pack2dup(float x) {
    u64 r; asm("mov.b64 %0, {%1, %1};" : "=l"(r) : "f"(x)); return r;
}
__device__ __forceinline__ void unpack2(u64 v, float &x, float &y) {
    asm("mov.b64 {%0, %1}, %2;" : "=f"(x), "=f"(y) : "l"(v));
}
// 128-bit shared load directly into two u64 (keeps FFMA2 operands paired)
__device__ __forceinline__ void lds128(u64 &lo, u64 &hi, const void* p) {
    unsigned s = (unsigned)__cvta_generic_to_shared(p);
    asm("ld.shared.v2.b64 {%0, %1}, [%2];" : "=l"(lo), "=l"(hi) : "r"(s));
}

// ---------------- precomputed per-batch tables ----------------
__device__ float g_ck[2][NSLOT][DD];   // SCALE * Wq^T k_j
__device__ float g_c0[2][NSLOT];       // SCALE * Wq_b . k_j
__device__ float g_M [2][NSLOT][DD];   // slots_full[j] @ out_w^T
__device__ float g_sscale;             // exp(density_scale)

__global__ void __launch_bounds__(576)
precompute_kernel(const float* __restrict__ slots,
                  const float* __restrict__ empty_slot,
                  const float* __restrict__ Wq_w,
                  const float* __restrict__ Wq_b,
                  const float* __restrict__ Wk_w,
                  const float* __restrict__ Wk_b,
                  const float* __restrict__ out_w,
                  const float* __restrict__ density_scale)
{
    const int b   = blockIdx.x;
    const int tid = threadIdx.x;
    __shared__ float sWk [64 * 65];      // padded stride 65 -> conflict-free d-major reads
    __shared__ float sOut[64 * 65];
    __shared__ float sWq [64 * 64];
    __shared__ float sf[NSLOT][DD];
    __shared__ float kv[NSLOT][DD];

    for (int i = tid; i < 4096; i += 576) {
        int r = i >> 6, c = i & 63;
        sWk [r * 65 + c] = Wk_w[i];
        sOut[r * 65 + c] = out_w[i];
        sWq [i]          = Wq_w[i];
    }
    for (int i = tid; i < NSLOT * DD; i += 576) {
        int j = i >> 6, s = i & 63;
        sf[j][s] = (j == 0) ? empty_slot[s]
                            : slots[((size_t)b * 8 + (j - 1)) * DD + s];
    }
    __syncthreads();

    const int j = tid >> 6;   // 0..8 (576 = 9*64 threads)
    const int d = tid & 63;
    {
        float aK = Wk_b[d], aM = 0.f;
        #pragma unroll 8
        for (int s = 0; s < DD; ++s) {
            float sv = sf[j][s];
            aK = fmaf(sv, sWk [d * 65 + s], aK);
            aM = fmaf(sv, sOut[d * 65 + s], aM);
        }
        kv[j][d]    = aK;
        g_M[b][j][d] = aM;
    }
    __syncthreads();
    {
        float a = 0.f;
        #pragma unroll 8
        for (int dd = 0; dd < DD; ++dd)
            a = fmaf(sWq[dd * 64 + d], kv[j][dd], a);
        g_ck[b][j][d] = a * 0.125f;
    }
    if (tid < NSLOT) {
        float a = 0.f;
        #pragma unroll 8
        for (int dd = 0; dd < DD; ++dd)
            a = fmaf(Wq_b[dd], kv[tid][dd], a);
        g_c0[b][tid] = a * 0.125f;
    }
    if (b == 0 && tid == 0) g_sscale = expf(density_scale[0]);
}

// ---------------- main per-point kernel ----------------
__global__ void __launch_bounds__(BLK, 5)
points_kernel(const float* __restrict__ x,
              const float* __restrict__ coor,
              float* __restrict__ xo,
              float* __restrict__ wout,
              float* __restrict__ sig,
              const float* __restrict__ out_b,
              int Npts)
{
    __shared__ float4 xs4[TILE * 16];          // 32 KB, xor-swizzled rows
    __shared__ float  wbuf[TILE * NSLOT];      // 4.5 KB, packed [pt][j]
    __shared__ float4 sCK4[NSLOT * 16];        // 2.25 KB
    __shared__ float  sC0[NSLOT];
    __shared__ float  sScale;

    const int b     = blockIdx.y;
    const int t     = threadIdx.x;
    const int tile0 = blockIdx.x * TILE;
    const int valid = min(TILE, Npts - tile0);
    const size_t base = (size_t)b * Npts + tile0;

    // load per-batch tables
    {
        const float4* gck = (const float4*)&g_ck[b][0][0];
        for (int i = t; i < NSLOT * 16; i += BLK) sCK4[i] = gck[i];
        if (t < NSLOT) sC0[t] = g_c0[b][t];
        if (t == 0)    sScale = g_sscale;
    }

    // ---- phase A: stage x tile (coalesced LDG, swizzled STS) ----
    {
        const float4* gx = (const float4*)(x + base * DD);
        #pragma unroll
        for (int kk = 0; kk < 16; ++kk) {
            int i   = kk * BLK + t;
            int row = i >> 4, ch = i & 15;
            if (row < valid)
                xs4[(row << 4) | (ch ^ (row & 7))] = gx[i];
        }
    }
    __syncthreads();

    // ---- phase B: logits + softmax + sigma + w (1 point / thread) ----
    if (t < valid) {
        u64 acc2[NSLOT];
        #pragma unroll
        for (int j = 0; j < NSLOT; ++j) acc2[j] = 0ull;   // (0.f, 0.f)

        const float4* xr = &xs4[t << 4];
        const int sw = t & 7;
        #pragma unroll
        for (int c = 0; c < 16; ++c) {
            u64 xlo, xhi;
            lds128(xlo, xhi, &xr[c ^ sw]);
            #pragma unroll
            for (int j = 0; j < NSLOT; ++j) {
                u64 clo, chi;
                lds128(clo, chi, &sCK4[j * 16 + c]);
                acc2[j] = ffma2(xlo, clo, acc2[j]);
                acc2[j] = ffma2(xhi, chi, acc2[j]);
            }
        }
        float lg[NSLOT];
        #pragma unroll
        for (int j = 0; j < NSLOT; ++j) {
            float lo, hi; unpack2(acc2[j], lo, hi);
            lg[j] = lo + hi + sC0[j];
        }

        const float* cp = coor + (base + t) * 3;
        bool oob = (fabsf(cp[0]) > 1.0f) || (fabsf(cp[1]) > 1.0f) || (fabsf(cp[2]) > 1.0f);
        const int kmax = oob ? 2 : NSLOT;

        float m = fmaxf(lg[0], lg[1]);
        if (!oob) {
            #pragma unroll
            for (int j = 2; j < NSLOT; ++j) m = fmaxf(m, lg[j]);
        }
        float w[NSLOT], sum = 0.f;
        #pragma unroll
        for (int j = 0; j < NSLOT; ++j) {
            float e = (j < kmax) ? __expf(lg[j] - m) : 0.f;
            w[j] = e; sum += e;
        }
        const float inv = __frcp_rn(sum);

        float sg = 0.f;
        #pragma unroll
        for (int j = 1; j < NSLOT; ++j)
            sg = fmaf(fmaxf(lg[j], 0.f), w[j], sg);
        sig[base + t] = sg * inv * sScale;

        #pragma unroll
        for (int j = 0; j < NSLOT; ++j)
            wbuf[t * NSLOT + j] = w[j] * inv;
    }
    __syncthreads();

    // ---- phase C: xo = w @ M + out_b ; thread = (point-group, 16B chunk) ----
    {
        const int g  = t >> 4;     // 0..7 : group of 16 points
        const int ch = t & 15;     // f4 chunk of the 64-float row
        u64 Mlo[NSLOT], Mhi[NSLOT];
        #pragma unroll
        for (int j = 0; j < NSLOT; ++j) {
            float4 mv = ((const float4*)&g_M[b][j][0])[ch];
            Mlo[j] = pack2(mv.x, mv.y);
            Mhi[j] = pack2(mv.z, mv.w);
        }
        float4 obv = ((const float4*)out_b)[ch];
        const u64 oblo = pack2(obv.x, obv.y), obhi = pack2(obv.z, obv.w);

        float4* go = (float4*)(xo + base * DD);
        #pragma unroll 4
        for (int i = 0; i < 16; ++i) {
            int pt = g * 16 + i;
            if (pt < valid) {
                const float* wp = &wbuf[pt * NSLOT];
                u64 olo = oblo, ohi = obhi;
                #pragma unroll
                for (int j = 0; j < NSLOT; ++j) {
                    u64 wj = pack2dup(wp[j]);
                    olo = ffma2(wj, Mlo[j], olo);
                    ohi = ffma2(wj, Mhi[j], ohi);
                }
                float4 o;
                unpack2(olo, o.x, o.y);
                unpack2(ohi, o.z, o.w);
                go[pt * 16 + ch] = o;     // lanes 0-15 = one contiguous row: coalesced
            }
        }
    }

    // ---- w: flat coalesced copy from shared ----
    {
        float* gw = wout + base * NSLOT;
        if (valid == TILE && ((base * NSLOT) & 3) == 0) {
            const float4* wb4 = (const float4*)wbuf;
            float4* gw4 = (float4*)gw;
            #pragma unroll
            for (int i = t; i < TILE * NSLOT / 4; i += BLK) gw4[i] = wb4[i];
        } else {
            for (int i = t; i < valid * NSLOT; i += BLK) gw[i] = wbuf[i];
        }
    }
}

extern "C" void kernel_launch(void* const* d_in, const int* in_sizes, int n_in,
                              void* d_out, int out_size)
{
    const float* point_feats   = (const float*)d_in[0];
    // d_in[1] = points_emb (unused by the scored block)
    const float* slots         = (const float*)d_in[2];
    const float* coor          = (const float*)d_in[3];
    const float* empty_slot    = (const float*)d_in[4];
    const float* Wq_w          = (const float*)d_in[5];
    const float* Wq_b          = (const float*)d_in[6];
    const float* Wk_w          = (const float*)d_in[7];
    const float* Wk_b          = (const float*)d_in[8];
    const float* out_w         = (const float*)d_in[9];
    const float* out_b         = (const float*)d_in[10];
    const float* density_scale = (const float*)d_in[11];

    const int B    = in_sizes[2] / (8 * 64);      // slots: [B, 8, 64]
    const int Npts = in_sizes[0] / (B * 64);      // point_feats: [B, N, 64]

    float* xo   = (float*)d_out;                                  // [B, N, 64]
    float* wout = xo + (size_t)B * Npts * 64;                     // [B, N, 9]
    float* sg   = wout + (size_t)B * Npts * 9;                    // [B, N]

    precompute_kernel<<<B, 576>>>(slots, empty_slot, Wq_w, Wq_b,
                                  Wk_w, Wk_b, out_w, density_scale);

    dim3 grid((Npts + TILE - 1) / TILE, B);
    points_kernel<<<grid, BLK>>>(point_feats, coor, xo, wout, sg, out_b, Npts);
}

// round 3
// speedup vs baseline: 2.0077x; 1.2413x over previous
#include <cuda_runtime.h>
#include <math.h>
#include <stdint.h>

#define NSLOT 9
#define DD    64
#define TILE  128   // points per block
#define BLK   128   // threads per block

typedef unsigned long long u64;

// ---------------- packed f32x2 helpers ----------------
__device__ __forceinline__ u64 ffma2(u64 a, u64 b, u64 c) {
    u64 d;
    asm("fma.rn.f32x2 %0, %1, %2, %3;" : "=l"(d) : "l"(a), "l"(b), "l"(c));
    return d;
}
__device__ __forceinline__ u64 pack2(float x, float y) {
    u64 r; asm("mov.b64 %0, {%1, %2};" : "=l"(r) : "f"(x), "f"(y)); return r;
}
__device__ __forceinline__ u64 pack2dup(float x) {
    u64 r; asm("mov.b64 %0, {%1, %1};" : "=l"(r) : "f"(x)); return r;
}
__device__ __forceinline__ void unpack2(u64 v, float &x, float &y) {
    asm("mov.b64 {%0, %1}, %2;" : "=f"(x), "=f"(y) : "l"(v));
}
__device__ __forceinline__ void lds128(u64 &lo, u64 &hi, const void* p) {
    unsigned s = (unsigned)__cvta_generic_to_shared(p);
    asm("ld.shared.v2.b64 {%0, %1}, [%2];" : "=l"(lo), "=l"(hi) : "r"(s));
}

// ---------------- precomputed per-batch tables ----------------
__device__ float g_ck[2][NSLOT][DD];   // SCALE * Wq^T k_j
__device__ float g_c0[2][NSLOT];       // SCALE * Wq_b . k_j
__device__ float g_M [2][NSLOT][DD];   // slots_full[j] @ out_w^T
__device__ float g_sscale;             // exp(density_scale)

// grid = (NSLOT, B), block = 64 : one (slot j, batch b) per block
__global__ void __launch_bounds__(64)
precompute_kernel(const float* __restrict__ slots,
                  const float* __restrict__ empty_slot,
                  const float* __restrict__ Wq_w,
                  const float* __restrict__ Wq_b,
                  const float* __restrict__ Wk_w,
                  const float* __restrict__ Wk_b,
                  const float* __restrict__ out_w,
                  const float* __restrict__ density_scale)
{
    const int j = blockIdx.x;
    const int b = blockIdx.y;
    const int d = threadIdx.x;            // 0..63
    __shared__ float sf[DD];
    __shared__ float kv[DD];

    sf[d] = (j == 0) ? empty_slot[d]
                     : slots[((size_t)b * 8 + (j - 1)) * DD + d];
    __syncthreads();

    // kv[d] = Wk_b[d] + sum_s sf[s]*Wk_w[d][s];  M = sum_s sf[s]*out_w[d][s]
    {
        const float4* wk4 = (const float4*)(Wk_w  + (size_t)d * DD);
        const float4* ow4 = (const float4*)(out_w + (size_t)d * DD);
        const float4* sf4 = (const float4*)sf;
        float aK = Wk_b[d], aM = 0.f;
        #pragma unroll
        for (int c = 0; c < 16; ++c) {
            float4 s4 = sf4[c];
            float4 k4 = wk4[c];
            float4 o4 = ow4[c];
            aK = fmaf(s4.x, k4.x, aK); aK = fmaf(s4.y, k4.y, aK);
            aK = fmaf(s4.z, k4.z, aK); aK = fmaf(s4.w, k4.w, aK);
            aM = fmaf(s4.x, o4.x, aM); aM = fmaf(s4.y, o4.y, aM);
            aM = fmaf(s4.z, o4.z, aM); aM = fmaf(s4.w, o4.w, aM);
        }
        kv[d] = aK;
        g_M[b][j][d] = aM;
    }
    __syncthreads();

    // ck[j][e] = 0.125 * sum_d Wq_w[d][e]*kv[d]   (column reads: coalesced)
    {
        float a = 0.f;
        #pragma unroll 8
        for (int dd = 0; dd < DD; ++dd)
            a = fmaf(Wq_w[(size_t)dd * DD + d], kv[dd], a);
        g_ck[b][j][d] = a * 0.125f;
    }
    if (d == 0) {
        float a = 0.f;
        #pragma unroll 8
        for (int dd = 0; dd < DD; ++dd)
            a = fmaf(Wq_b[dd], kv[dd], a);
        g_c0[b][j] = a * 0.125f;
        if (b == 0 && j == 0) g_sscale = expf(density_scale[0]);
    }
}

// ---------------- main per-point kernel ----------------
__global__ void __launch_bounds__(BLK, 5)
points_kernel(const float* __restrict__ x,
              const float* __restrict__ coor,
              float* __restrict__ xo,
              float* __restrict__ wout,
              float* __restrict__ sig,
              const float* __restrict__ out_b,
              int Npts)
{
    __shared__ float4 xs4[TILE * 16];          // 32 KB, xor-swizzled rows
    __shared__ float  wbuf[TILE * 12];         // 6 KB, stride-12 padded [pt][0..8,pad3]
    __shared__ float4 sCK4[NSLOT * 16];        // 2.25 KB
    __shared__ float  sC0[NSLOT];
    __shared__ float  sScale;

    const int b     = blockIdx.y;
    const int t     = threadIdx.x;
    const int tile0 = blockIdx.x * TILE;
    const int valid = min(TILE, Npts - tile0);
    const size_t base = (size_t)b * Npts + tile0;

    {
        const float4* gck = (const float4*)&g_ck[b][0][0];
        for (int i = t; i < NSLOT * 16; i += BLK) sCK4[i] = gck[i];
        if (t < NSLOT) sC0[t] = g_c0[b][t];
        if (t == 0)    sScale = g_sscale;
    }

    // ---- phase A: stage x tile (coalesced LDG, swizzled STS) ----
    {
        const float4* gx = (const float4*)(x + base * DD);
        #pragma unroll
        for (int kk = 0; kk < 16; ++kk) {
            int i   = kk * BLK + t;
            int row = i >> 4, ch = i & 15;
            if (row < valid)
                xs4[(row << 4) | (ch ^ (row & 7))] = gx[i];
        }
    }
    __syncthreads();

    // ---- phase B: 2 points / thread (threads 0..63) ----
    if (t < 64) {
        const int p0 = t, p1 = t + 64;
        const bool v1 = (p1 < valid);
        u64 accA[NSLOT], accB[NSLOT];
        #pragma unroll
        for (int j = 0; j < NSLOT; ++j) { accA[j] = 0ull; accB[j] = 0ull; }

        const float4* xr0 = &xs4[p0 << 4];
        const float4* xr1 = &xs4[p1 << 4];
        const int sw = t & 7;                  // same swizzle for p0 and p1
        #pragma unroll
        for (int c = 0; c < 16; ++c) {
            u64 a_lo, a_hi, b_lo, b_hi;
            lds128(a_lo, a_hi, &xr0[c ^ sw]);
            lds128(b_lo, b_hi, &xr1[c ^ sw]);
            #pragma unroll
            for (int j = 0; j < NSLOT; ++j) {
                u64 clo, chi;
                lds128(clo, chi, &sCK4[j * 16 + c]);
                accA[j] = ffma2(a_lo, clo, accA[j]);
                accA[j] = ffma2(a_hi, chi, accA[j]);
                accB[j] = ffma2(b_lo, clo, accB[j]);
                accB[j] = ffma2(b_hi, chi, accB[j]);
            }
        }

        #pragma unroll
        for (int pp = 0; pp < 2; ++pp) {
            const int p = pp ? p1 : p0;
            if (pp && !v1) break;
            if (p >= valid) continue;
            float lg[NSLOT];
            #pragma unroll
            for (int j = 0; j < NSLOT; ++j) {
                float lo, hi;
                unpack2(pp ? accB[j] : accA[j], lo, hi);
                lg[j] = lo + hi + sC0[j];
            }

            const float* cp = coor + (base + p) * 3;
            bool oob = (fabsf(cp[0]) > 1.0f) || (fabsf(cp[1]) > 1.0f) || (fabsf(cp[2]) > 1.0f);
            const int kmax = oob ? 2 : NSLOT;

            float m = fmaxf(lg[0], lg[1]);
            if (!oob) {
                #pragma unroll
                for (int j = 2; j < NSLOT; ++j) m = fmaxf(m, lg[j]);
            }
            float w[NSLOT], sum = 0.f;
            #pragma unroll
            for (int j = 0; j < NSLOT; ++j) {
                float e = (j < kmax) ? __expf(lg[j] - m) : 0.f;
                w[j] = e; sum += e;
            }
            const float inv = __frcp_rn(sum);

            float sg = 0.f;
            #pragma unroll
            for (int j = 1; j < NSLOT; ++j)
                sg = fmaf(fmaxf(lg[j], 0.f), w[j], sg);
            sig[base + p] = sg * inv * sScale;

            float* wp = &wbuf[p * 12];
            ((float4*)wp)[0] = make_float4(w[0]*inv, w[1]*inv, w[2]*inv, w[3]*inv);
            ((float4*)wp)[1] = make_float4(w[4]*inv, w[5]*inv, w[6]*inv, w[7]*inv);
            ((float4*)wp)[2] = make_float4(w[8]*inv, 0.f, 0.f, 0.f);
        }
    }
    __syncthreads();

    // ---- phase C: xo = w @ M + out_b; also emit w to global ----
    {
        const int g  = t >> 4;     // 0..7 : group of 16 points
        const int ch = t & 15;     // f4 chunk of the 64-float row
        u64 Mlo[NSLOT], Mhi[NSLOT];
        #pragma unroll
        for (int j = 0; j < NSLOT; ++j) {
            float4 mv = ((const float4*)&g_M[b][j][0])[ch];
            Mlo[j] = pack2(mv.x, mv.y);
            Mhi[j] = pack2(mv.z, mv.w);
        }
        float4 obv = ((const float4*)out_b)[ch];
        const u64 oblo = pack2(obv.x, obv.y), obhi = pack2(obv.z, obv.w);

        float4* go = (float4*)(xo + base * DD);
        float*  gw = wout + base * (size_t)NSLOT;
        #pragma unroll 4
        for (int i = 0; i < 16; ++i) {
            int pt = g * 16 + i;
            if (pt < valid) {
                const float* wp = &wbuf[pt * 12];
                u64 w01, w23, w45, w67, w8x;
                lds128(w01, w23, wp);
                lds128(w45, w67, wp + 4);
                float w0,w1,w2,w3,w4,w5,w6,w7,w8;
                unpack2(w01, w0, w1); unpack2(w23, w2, w3);
                unpack2(w45, w4, w5); unpack2(w67, w6, w7);
                w8 = wp[8];
                float wv[NSLOT] = {w0,w1,w2,w3,w4,w5,w6,w7,w8};

                u64 olo = oblo, ohi = obhi;
                #pragma unroll
                for (int j = 0; j < NSLOT; ++j) {
                    u64 wj = pack2dup(wv[j]);
                    olo = ffma2(wj, Mlo[j], olo);
                    ohi = ffma2(wj, Mhi[j], ohi);
                }
                float4 o;
                unpack2(olo, o.x, o.y);
                unpack2(ohi, o.z, o.w);
                go[pt * 16 + ch] = o;                 // lanes 0-15 one row: coalesced

                if (ch < NSLOT)                       // emit w (9 lanes x 2 groups)
                    gw[(size_t)pt * NSLOT + ch] = wbuf[pt * 12 + ch];
            }
        }
    }
}

extern "C" void kernel_launch(void* const* d_in, const int* in_sizes, int n_in,
                              void* d_out, int out_size)
{
    const float* point_feats   = (const float*)d_in[0];
    // d_in[1] = points_emb (unused by the scored block)
    const float* slots         = (const float*)d_in[2];
    const float* coor          = (const float*)d_in[3];
    const float* empty_slot    = (const float*)d_in[4];
    const float* Wq_w          = (const float*)d_in[5];
    const float* Wq_b          = (const float*)d_in[6];
    const float* Wk_w          = (const float*)d_in[7];
    const float* Wk_b          = (const float*)d_in[8];
    const float* out_w         = (const float*)d_in[9];
    const float* out_b         = (const float*)d_in[10];
    const float* density_scale = (const float*)d_in[11];

    const int B    = in_sizes[2] / (8 * 64);      // slots: [B, 8, 64]
    const int Npts = in_sizes[0] / (B * 64);      // point_feats: [B, N, 64]

    float* xo   = (float*)d_out;                                  // [B, N, 64]
    float* wout = xo + (size_t)B * Npts * 64;                     // [B, N, 9]
    float* sg   = wout + (size_t)B * Npts * 9;                    // [B, N]

    dim3 pgrid(NSLOT, B);
    precompute_kernel<<<pgrid, 64>>>(slots, empty_slot, Wq_w, Wq_b,
                                     Wk_w, Wk_b, out_w, density_scale);

    dim3 grid((Npts + TILE - 1) / TILE, B);
    points_kernel<<<grid, BLK>>>(point_feats, coor, xo, wout, sg, out_b, Npts);
}

// round 5
// speedup vs baseline: 2.1364x; 1.0641x over previous
#include <cuda_runtime.h>
#include <math.h>
#include <stdint.h>

#define NSLOT 9
#define DD    64
#define TILE  128   // points per block
#define BLK   128   // threads per block

typedef unsigned long long u64;

// ---------------- packed f32x2 helpers ----------------
__device__ __forceinline__ u64 ffma2(u64 a, u64 b, u64 c) {
    u64 d;
    asm("fma.rn.f32x2 %0, %1, %2, %3;" : "=l"(d) : "l"(a), "l"(b), "l"(c));
    return d;
}
__device__ __forceinline__ u64 pack2(float x, float y) {
    u64 r; asm("mov.b64 %0, {%1, %2};" : "=l"(r) : "f"(x), "f"(y)); return r;
}
__device__ __forceinline__ u64 pack2dup(float x) {
    u64 r; asm("mov.b64 %0, {%1, %1};" : "=l"(r) : "f"(x)); return r;
}
__device__ __forceinline__ void unpack2(u64 v, float &x, float &y) {
    asm("mov.b64 {%0, %1}, %2;" : "=f"(x), "=f"(y) : "l"(v));
}
__device__ __forceinline__ void lds128(u64 &lo, u64 &hi, const void* p) {
    unsigned s = (unsigned)__cvta_generic_to_shared(p);
    asm("ld.shared.v2.b64 {%0, %1}, [%2];" : "=l"(lo), "=l"(hi) : "r"(s));
}

// ---------------- precomputed per-batch tables ----------------
__device__ float g_ck[2][NSLOT][DD];   // SCALE * Wq^T k_j
__device__ float g_c0[2][NSLOT];       // SCALE * Wq_b . k_j
__device__ float g_M [2][NSLOT][DD];   // slots_full[j] @ out_w^T
__device__ float g_sscale;             // exp(density_scale)

// grid = (NSLOT, B), block = 64 : one (slot j, batch b) per block
__global__ void __launch_bounds__(64)
precompute_kernel(const float* __restrict__ slots,
                  const float* __restrict__ empty_slot,
                  const float* __restrict__ Wq_w,
                  const float* __restrict__ Wq_b,
                  const float* __restrict__ Wk_w,
                  const float* __restrict__ Wk_b,
                  const float* __restrict__ out_w,
                  const float* __restrict__ density_scale)
{
    const int j = blockIdx.x;
    const int b = blockIdx.y;
    const int d = threadIdx.x;            // 0..63
    __shared__ float sf[DD];
    __shared__ float kv[DD];

    sf[d] = (j == 0) ? empty_slot[d]
                     : slots[((size_t)b * 8 + (j - 1)) * DD + d];
    __syncthreads();

    {
        const float4* wk4 = (const float4*)(Wk_w  + (size_t)d * DD);
        const float4* ow4 = (const float4*)(out_w + (size_t)d * DD);
        const float4* sf4 = (const float4*)sf;
        float aK = Wk_b[d], aM = 0.f;
        #pragma unroll
        for (int c = 0; c < 16; ++c) {
            float4 s4 = sf4[c];
            float4 k4 = wk4[c];
            float4 o4 = ow4[c];
            aK = fmaf(s4.x, k4.x, aK); aK = fmaf(s4.y, k4.y, aK);
            aK = fmaf(s4.z, k4.z, aK); aK = fmaf(s4.w, k4.w, aK);
            aM = fmaf(s4.x, o4.x, aM); aM = fmaf(s4.y, o4.y, aM);
            aM = fmaf(s4.z, o4.z, aM); aM = fmaf(s4.w, o4.w, aM);
        }
        kv[d] = aK;
        g_M[b][j][d] = aM;
    }
    __syncthreads();

    {
        float a = 0.f;
        #pragma unroll 8
        for (int dd = 0; dd < DD; ++dd)
            a = fmaf(Wq_w[(size_t)dd * DD + d], kv[dd], a);
        g_ck[b][j][d] = a * 0.125f;
    }
    if (d == 0) {
        float a = 0.f;
        #pragma unroll 8
        for (int dd = 0; dd < DD; ++dd)
            a = fmaf(Wq_b[dd], kv[dd], a);
        g_c0[b][j] = a * 0.125f;
        if (b == 0 && j == 0) g_sscale = expf(density_scale[0]);
    }
}

// ---------------- main per-point kernel ----------------
__global__ void __launch_bounds__(BLK, 5)
points_kernel(const float* __restrict__ x,
              const float* __restrict__ coor,
              float* __restrict__ xo,
              float* __restrict__ wout,
              float* __restrict__ sig,
              const float* __restrict__ out_b,
              int Npts)
{
    __shared__ float4 xs4[TILE * 16];          // 32 KB, xor-swizzled rows
    __shared__ float  wbuf[TILE * 12];         // 6 KB, stride-12 padded
    __shared__ float4 sCK4[NSLOT * 16];        // 2.25 KB
    __shared__ float  sC0[NSLOT];
    __shared__ float  sScale;

    const int b     = blockIdx.y;
    const int t     = threadIdx.x;
    const int tile0 = blockIdx.x * TILE;
    const int valid = min(TILE, Npts - tile0);
    const size_t base = (size_t)b * Npts + tile0;

    // prefetch coor early (latency hidden behind staging loop)
    float cx = 0.f, cy = 0.f, cz = 0.f;
    if (t < valid) {
        const float* cp = coor + (base + t) * 3;
        cx = cp[0]; cy = cp[1]; cz = cp[2];
    }

    {
        const float4* gck = (const float4*)&g_ck[b][0][0];
        for (int i = t; i < NSLOT * 16; i += BLK) sCK4[i] = gck[i];
        if (t < NSLOT) sC0[t] = g_c0[b][t];
        if (t == 0)    sScale = g_sscale;
    }

    // ---- phase A: stage x tile (coalesced LDG, swizzled STS) ----
    {
        const float4* gx = (const float4*)(x + base * DD);
        #pragma unroll
        for (int kk = 0; kk < 16; ++kk) {
            int i   = kk * BLK + t;
            int row = i >> 4, ch = i & 15;
            if (row < valid)
                xs4[(row << 4) | (ch ^ (row & 7))] = gx[i];
        }
    }
    __syncthreads();

    // ---- phase B: 1 point / thread, ALL 128 threads (all 4 SMSPs fed) ----
    if (t < valid) {
        u64 acc[NSLOT];
        #pragma unroll
        for (int j = 0; j < NSLOT; ++j) acc[j] = 0ull;

        const float4* xr = &xs4[t << 4];
        const int sw = t & 7;
        #pragma unroll
        for (int c = 0; c < 16; ++c) {
            u64 xlo, xhi;
            lds128(xlo, xhi, &xr[c ^ sw]);
            #pragma unroll
            for (int j = 0; j < NSLOT; ++j) {
                u64 clo, chi;
                lds128(clo, chi, &sCK4[j * 16 + c]);
                acc[j] = ffma2(xlo, clo, acc[j]);
                acc[j] = ffma2(xhi, chi, acc[j]);
            }
        }
        float lg[NSLOT];
        #pragma unroll
        for (int j = 0; j < NSLOT; ++j) {
            float lo, hi; unpack2(acc[j], lo, hi);
            lg[j] = lo + hi + sC0[j];
        }

        bool oob = (fabsf(cx) > 1.0f) || (fabsf(cy) > 1.0f) || (fabsf(cz) > 1.0f);
        const int kmax = oob ? 2 : NSLOT;

        float m = fmaxf(lg[0], lg[1]);
        if (!oob) {
            #pragma unroll
            for (int j = 2; j < NSLOT; ++j) m = fmaxf(m, lg[j]);
        }
        float w[NSLOT], sum = 0.f;
        #pragma unroll
        for (int j = 0; j < NSLOT; ++j) {
            float e = (j < kmax) ? __expf(lg[j] - m) : 0.f;
            w[j] = e; sum += e;
        }
        const float inv = __frcp_rn(sum);

        float sg = 0.f;
        #pragma unroll
        for (int j = 1; j < NSLOT; ++j)
            sg = fmaf(fmaxf(lg[j], 0.f), w[j], sg);
        sig[base + t] = sg * inv * sScale;

        float* wp = &wbuf[t * 12];
        ((float4*)wp)[0] = make_float4(w[0]*inv, w[1]*inv, w[2]*inv, w[3]*inv);
        ((float4*)wp)[1] = make_float4(w[4]*inv, w[5]*inv, w[6]*inv, w[7]*inv);
        ((float4*)wp)[2] = make_float4(w[8]*inv, 0.f, 0.f, 0.f);
    }
    __syncthreads();

    // ---- phase C: xo = w @ M + out_b; also emit w to global ----
    {
        const int g  = t >> 4;     // 0..7 : group of 16 points
        const int ch = t & 15;     // f4 chunk of the 64-float row
        u64 Mlo[NSLOT], Mhi[NSLOT];
        #pragma unroll
        for (int j = 0; j < NSLOT; ++j) {
            float4 mv = ((const float4*)&g_M[b][j][0])[ch];
            Mlo[j] = pack2(mv.x, mv.y);
            Mhi[j] = pack2(mv.z, mv.w);
        }
        float4 obv = ((const float4*)out_b)[ch];
        const u64 oblo = pack2(obv.x, obv.y), obhi = pack2(obv.z, obv.w);

        float4* go = (float4*)(xo + base * DD);
        float*  gw = wout + base * (size_t)NSLOT;
        #pragma unroll 4
        for (int i = 0; i < 16; ++i) {
            int pt = g * 16 + i;
            if (pt < valid) {
                const float* wp = &wbuf[pt * 12];
                u64 w01, w23, w45, w67;
                lds128(w01, w23, wp);
                lds128(w45, w67, wp + 4);
                float w0,w1,w2,w3,w4,w5,w6,w7,w8;
                unpack2(w01, w0, w1); unpack2(w23, w2, w3);
                unpack2(w45, w4, w5); unpack2(w67, w6, w7);
                w8 = wp[8];
                float wv[NSLOT] = {w0,w1,w2,w3,w4,w5,w6,w7,w8};

                u64 olo = oblo, ohi = obhi;
                #pragma unroll
                for (int j = 0; j < NSLOT; ++j) {
                    u64 wj = pack2dup(wv[j]);
                    olo = ffma2(wj, Mlo[j], olo);
                    ohi = ffma2(wj, Mhi[j], ohi);
                }
                float4 o;
                unpack2(olo, o.x, o.y);
                unpack2(ohi, o.z, o.w);
                go[pt * 16 + ch] = o;                 // lanes 0-15 one row: coalesced

                if (ch < NSLOT)
                    gw[(size_t)pt * NSLOT + ch] = wbuf[pt * 12 + ch];
            }
        }
    }
}

extern "C" void kernel_launch(void* const* d_in, const int* in_sizes, int n_in,
                              void* d_out, int out_size)
{
    const float* point_feats   = (const float*)d_in[0];
    // d_in[1] = points_emb (unused by the scored block)
    const float* slots         = (const float*)d_in[2];
    const float* coor          = (const float*)d_in[3];
    const float* empty_slot    = (const float*)d_in[4];
    const float* Wq_w          = (const float*)d_in[5];
    const float* Wq_b          = (const float*)d_in[6];
    const float* Wk_w          = (const float*)d_in[7];
    const float* Wk_b          = (const float*)d_in[8];
    const float* out_w         = (const float*)d_in[9];
    const float* out_b         = (const float*)d_in[10];
    const float* density_scale = (const float*)d_in[11];

    const int B    = in_sizes[2] / (8 * 64);      // slots: [B, 8, 64]
    const int Npts = in_sizes[0] / (B * 64);      // point_feats: [B, N, 64]

    float* xo   = (float*)d_out;                                  // [B, N, 64]
    float* wout = xo + (size_t)B * Npts * 64;                     // [B, N, 9]
    float* sg   = wout + (size_t)B * Npts * 9;                    // [B, N]

    dim3 pgrid(NSLOT, B);
    precompute_kernel<<<pgrid, 64>>>(slots, empty_slot, Wq_w, Wq_b,
                                     Wk_w, Wk_b, out_w, density_scale);

    dim3 grid((Npts + TILE - 1) / TILE, B);
    points_kernel<<<grid, BLK>>>(point_feats, coor, xo, wout, sg, out_b, Npts);
}